// round 9
// baseline (speedup 1.0000x reference)
#include <cuda_runtime.h>
#include <cuda_fp16.h>
#include <cstdint>

// Problem dims (fixed)
#define BB 4
#define TT 4096
#define HH 2048
#define LL 4
#define MROWS 16384
#define N3H 6144
#define KDIM 2048

// GEMM tiling: CTA 128x128, BK=16, 2-stage cp.async, 8 warps (4x2), warp 32x64
#define BKT 16
#define NITER (KDIM / BKT)          // 128
#define TILE_B 4096                 // 128 rows x 32 bytes
#define STAGE_B (4 * TILE_B)        // Ah, Al, Bh, Bl = 16 KB

// ---------------- scratch (__device__ globals; referenced ONLY in device code)
__device__ float  g_BCx[(size_t)MROWS * N3H];     // 384 MB fp32
__device__ __half g_xh[(size_t)MROWS * HH];
__device__ __half g_xl[(size_t)MROWS * HH];
__device__ __half g_yh[(size_t)MROWS * HH];
__device__ __half g_yl[(size_t)MROWS * HH];
__device__ __half g_Wint_h[(size_t)N3H * HH];     // W_in^T  [6144][2048]
__device__ __half g_Wint_l[(size_t)N3H * HH];
__device__ __half g_Wot_h[(size_t)HH * HH];       // W_out^T [2048][2048]
__device__ __half g_Wot_l[(size_t)HH * HH];

// ---------------- PTX helpers (plain sm_103-safe) ----------------------------
__device__ __forceinline__ uint32_t smem_u32(const void* p) {
    uint32_t a;
    asm("{ .reg .u64 t; cvta.to.shared.u64 t, %1; cvt.u32.u64 %0, t; }" : "=r"(a) : "l"(p));
    return a;
}
// swizzle for 32B-row tiles: spread 16B chunks so 8 ldmatrix rows hit 8 slots
#define SWZ32(off) ((off) ^ (((off) >> 3) & 0x10))

#define CP_ASYNC16(dst, src) \
    asm volatile("cp.async.cg.shared.global [%0], [%1], 16;" :: "r"(dst), "l"(src))
#define CP_ASYNC_COMMIT() asm volatile("cp.async.commit_group;")
#define CP_ASYNC_WAIT(n)  asm volatile("cp.async.wait_group %0;" :: "n"(n))

#define LDSM_X4(r0, r1, r2, r3, addr) \
    asm volatile("ldmatrix.sync.aligned.m8n8.x4.shared.b16 {%0,%1,%2,%3}, [%4];" \
        : "=r"(r0), "=r"(r1), "=r"(r2), "=r"(r3) : "r"(addr))

// NOTE: NOT volatile — pure register computation; ptxas may reorder/schedule.
#define MMA16816(d, a, b0, b1) \
    asm("mma.sync.aligned.m16n8k16.row.col.f32.f16.f16.f32 " \
        "{%0,%1,%2,%3}, {%4,%5,%6,%7}, {%8,%9}, {%0,%1,%2,%3};" \
        : "+f"((d)[0]), "+f"((d)[1]), "+f"((d)[2]), "+f"((d)[3]) \
        : "r"((a)[0]), "r"((a)[1]), "r"((a)[2]), "r"((a)[3]), "r"(b0), "r"(b1))

// ---------------- prep kernels ----------------------------------------------
__global__ __launch_bounds__(256)
void split_x_kernel(const float* __restrict__ x)
{
    size_t i = ((size_t)blockIdx.x * 256 + threadIdx.x) * 4;
    float4 v = *(const float4*)(x + i);
    float f[4] = {v.x, v.y, v.z, v.w};
    __half h[4], l[4];
    #pragma unroll
    for (int j = 0; j < 4; ++j) {
        h[j] = __float2half(f[j]);
        l[j] = __float2half(f[j] - __half2float(h[j]));
    }
    *(uint2*)(g_xh + i) = *(uint2*)h;
    *(uint2*)(g_xl + i) = *(uint2*)l;
}

// transpose + split: in fp32 [R][C] -> (device-global) oh/ol fp16 [C][R]
__global__ __launch_bounds__(256)
void transpose_split_kernel(const float* __restrict__ in, int wsel, int R, int C)
{
    __half* __restrict__ oh = wsel ? g_Wot_h : g_Wint_h;
    __half* __restrict__ ol = wsel ? g_Wot_l : g_Wint_l;

    __shared__ float tile[32][33];
    int tx = threadIdx.x, ty = threadIdx.y;
    int x = blockIdx.x * 32 + tx;
    int y0 = blockIdx.y * 32;
    #pragma unroll
    for (int j = ty; j < 32; j += 8)
        tile[j][tx] = in[(size_t)(y0 + j) * C + x];
    __syncthreads();
    int ox = y0 + tx;
    int oy0 = blockIdx.x * 32;
    #pragma unroll
    for (int j = ty; j < 32; j += 8) {
        float v = tile[tx][j];
        __half h = __float2half(v);
        __half l = __float2half(v - __half2float(h));
        size_t o = (size_t)(oy0 + j) * R + ox;
        oh[o] = h; ol[o] = l;
    }
}

// ---------------- split-precision fp16 mma.sync GEMM ------------------------
__device__ __forceinline__ void load_stage16(
    char* sbase, int k0, int bm, int bn,
    const __half* __restrict__ Ah, const __half* __restrict__ Al,
    const __half* __restrict__ Bh, const __half* __restrict__ Bl, int tid)
{
    const __half* srcs[4] = {Ah, Al, Bh, Bl};
    const int r = tid >> 1;          // row 0..127
    const int ch = tid & 1;          // 16B chunk 0..1
    #pragma unroll
    for (int sub = 0; sub < 4; ++sub) {
        const int rowbase = (sub < 2) ? bm : bn;
        uint32_t dst = smem_u32(sbase + sub * TILE_B);
        const __half* src = srcs[sub] + (size_t)(rowbase + r) * KDIM + k0 + ch * 8;
        CP_ASYNC16(dst + SWZ32(r * 32 + ch * 16), src);
    }
    CP_ASYNC_COMMIT();
}

// gsel: 0 -> A=g_xh/g_xl, B=g_Wint_*, C=g_BCx (Cw=N3H)
//       1 -> A=g_yh/g_yl, B=g_Wot_*,  C=Cout  (Cw=HH)
__global__ __launch_bounds__(256, 1)
void gemm_mma_kernel(int gsel, float* __restrict__ Cout)
{
    const __half* __restrict__ Ah = gsel ? g_yh : g_xh;
    const __half* __restrict__ Al = gsel ? g_yl : g_xl;
    const __half* __restrict__ Bh = gsel ? g_Wot_h : g_Wint_h;
    const __half* __restrict__ Bl = gsel ? g_Wot_l : g_Wint_l;
    float* __restrict__ C  = gsel ? Cout : g_BCx;
    const int Cw = gsel ? HH : N3H;

    __shared__ __align__(1024) char smem[2 * STAGE_B];   // 32 KB static
    const int tid = threadIdx.x;
    const int wid = tid >> 5;
    const int lid = tid & 31;
    const int wm = wid & 3;           // 4 warps in M -> 32 rows each
    const int wn = wid >> 2;          // 2 warps in N -> 64 cols each
    const int bm = blockIdx.y * 128;
    const int bn = blockIdx.x * 128;

    float acc[2][8][4];
    #pragma unroll
    for (int t = 0; t < 2; ++t)
        #pragma unroll
        for (int j = 0; j < 8; ++j)
            #pragma unroll
            for (int e = 0; e < 4; ++e) acc[t][j][e] = 0.f;

    // ldmatrix lane address components (tile-local)
    const int a_row = (lid & 15);
    const int a_kb  = (lid & 16) ? 16 : 0;
    const int b_row = (lid & 7) + ((lid & 16) ? 8 : 0);
    const int b_kb  = (lid & 8) ? 16 : 0;

    // prologue: 2 stages in flight
    load_stage16(smem,           0,   bm, bn, Ah, Al, Bh, Bl, tid);
    load_stage16(smem + STAGE_B, BKT, bm, bn, Ah, Al, Bh, Bl, tid);

    for (int i = 0; i < NITER; ++i) {
        if (i + 2 < NITER) { CP_ASYNC_WAIT(1); } else { CP_ASYNC_WAIT(0); }
        __syncthreads();

        char* sbase = smem + (i & 1) * STAGE_B;
        const uint32_t tAh = smem_u32(sbase);
        const uint32_t tAl = tAh + TILE_B;
        const uint32_t tBh = tAh + 2 * TILE_B;
        const uint32_t tBl = tAh + 3 * TILE_B;

        uint32_t ah[2][4], al[2][4], bh[4][4], bl[4][4];
        #pragma unroll
        for (int t = 0; t < 2; ++t) {
            int row = wm * 32 + t * 16 + a_row;
            LDSM_X4(ah[t][0], ah[t][1], ah[t][2], ah[t][3], tAh + SWZ32(row * 32 + a_kb));
            LDSM_X4(al[t][0], al[t][1], al[t][2], al[t][3], tAl + SWZ32(row * 32 + a_kb));
        }
        #pragma unroll
        for (int g = 0; g < 4; ++g) {
            int row = wn * 64 + g * 16 + b_row;
            LDSM_X4(bh[g][0], bh[g][1], bh[g][2], bh[g][3], tBh + SWZ32(row * 32 + b_kb));
            LDSM_X4(bl[g][0], bl[g][1], bl[g][2], bl[g][3], tBl + SWZ32(row * 32 + b_kb));
        }

        // pass-major ordering: within each pass all 16 MMAs hit distinct
        // accumulators -> RAW dependency distance 16 instead of 2.
        #pragma unroll
        for (int t = 0; t < 2; ++t)      // pass 1: Ah * Bh
            #pragma unroll
            for (int g = 0; g < 4; ++g) {
                MMA16816(acc[t][2 * g],     ah[t], bh[g][0], bh[g][1]);
                MMA16816(acc[t][2 * g + 1], ah[t], bh[g][2], bh[g][3]);
            }
        #pragma unroll
        for (int t = 0; t < 2; ++t)      // pass 2: Ah * Bl
            #pragma unroll
            for (int g = 0; g < 4; ++g) {
                MMA16816(acc[t][2 * g],     ah[t], bl[g][0], bl[g][1]);
                MMA16816(acc[t][2 * g + 1], ah[t], bl[g][2], bl[g][3]);
            }
        #pragma unroll
        for (int t = 0; t < 2; ++t)      // pass 3: Al * Bh
            #pragma unroll
            for (int g = 0; g < 4; ++g) {
                MMA16816(acc[t][2 * g],     al[t], bh[g][0], bh[g][1]);
                MMA16816(acc[t][2 * g + 1], al[t], bh[g][2], bh[g][3]);
            }

        __syncthreads();
        if (i + 2 < NITER)
            load_stage16(smem + (i & 1) * STAGE_B, (i + 2) * BKT, bm, bn, Ah, Al, Bh, Bl, tid);
    }

    // epilogue: fp32 accum -> C
    const int r0 = bm + wm * 32 + (lid >> 2);
    const int cb = bn + wn * 64 + (lid & 3) * 2;
    #pragma unroll
    for (int t = 0; t < 2; ++t)
        #pragma unroll
        for (int j = 0; j < 8; ++j) {
            float2 v0 = make_float2(acc[t][j][0], acc[t][j][1]);
            float2 v1 = make_float2(acc[t][j][2], acc[t][j][3]);
            *(float2*)(C + (size_t)(r0 + t * 16)     * Cw + cb + j * 8) = v0;
            *(float2*)(C + (size_t)(r0 + t * 16 + 8) * Cw + cb + j * 8) = v1;
        }
}

// ---------------- fused gate + mask + causal conv + Cg gate -----------------
#define CONV_CHUNK 128

__global__ __launch_bounds__(256)
void conv_kernel(const int* __restrict__ mask, const float* __restrict__ conv_w)
{
    const int h  = blockIdx.x * 256 + threadIdx.x;
    const int b  = blockIdx.z;
    const int t0 = blockIdx.y * CONV_CHUNK;

    const float cw0 = conv_w[h * LL + 0];
    const float cw1 = conv_w[h * LL + 1];
    const float cw2 = conv_w[h * LL + 2];
    const float cw3 = conv_w[h * LL + 3];

    float p1 = 0.f, p2 = 0.f, p3 = 0.f;
    #pragma unroll
    for (int d = 3; d >= 1; --d) {
        int t = t0 - d;
        float bx = 0.f;
        if (t >= 0 && mask[b * TT + t] != 0) {
            size_t base = ((size_t)(b * TT + t)) * N3H;
            bx = g_BCx[base + h] * g_BCx[base + 2 * HH + h];
        }
        p3 = p2; p2 = p1; p1 = bx;
    }

    for (int t = t0; t < t0 + CONV_CHUNK; ++t) {
        size_t base = ((size_t)(b * TT + t)) * N3H;
        float Bg = g_BCx[base + h];
        float Cg = g_BCx[base + HH + h];
        float xg = g_BCx[base + 2 * HH + h];
        float bx = (mask[b * TT + t] != 0) ? (Bg * xg) : 0.f;
        float conv = cw0 * p3 + cw1 * p2 + cw2 * p1 + cw3 * bx;
        float y = Cg * conv;
        size_t o = ((size_t)(b * TT + t)) * HH + h;
        __half hh = __float2half(y);
        g_yh[o] = hh;
        g_yl[o] = __float2half(y - __half2float(hh));
        p3 = p2; p2 = p1; p1 = bx;
    }
}

// ---------------- launch -----------------------------------------------------
extern "C" void kernel_launch(void* const* d_in, const int* in_sizes, int n_in,
                              void* d_out, int out_size)
{
    const float* x      = (const float*)d_in[0];
    const int*   mask   = (const int*)d_in[1];    // bool widened to int32
    const float* W_in   = (const float*)d_in[2];
    const float* conv_w = (const float*)d_in[3];
    const float* W_out  = (const float*)d_in[4];
    float*       out    = (float*)d_out;

    // prep: split x, transpose+split weights (globals selected device-side)
    split_x_kernel<<<(size_t)MROWS * HH / (256 * 4), 256>>>(x);
    transpose_split_kernel<<<dim3(N3H / 32, HH / 32), dim3(32, 8)>>>(W_in, 0, HH, N3H);
    transpose_split_kernel<<<dim3(HH / 32, HH / 32), dim3(32, 8)>>>(W_out, 1, HH, HH);

    // GEMM1: BCx = x @ W_in   (16384x2048 @ 2048x6144)
    gemm_mma_kernel<<<dim3(N3H / 128, MROWS / 128), 256>>>(0, nullptr);

    // gate + conv + gate -> y (split fp16)
    conv_kernel<<<dim3(HH / 256, TT / CONV_CHUNK, BB), 256>>>(mask, conv_w);

    // GEMM2: out = y @ W_out  (16384x2048 @ 2048x2048)
    gemm_mma_kernel<<<dim3(HH / 128, MROWS / 128), 256>>>(1, out);
}

// round 10
// speedup vs baseline: 2.1283x; 2.1283x over previous
#include <cuda_runtime.h>
#include <cuda_fp16.h>
#include <cstdint>

// Problem dims (fixed)
#define BB 4
#define TT 4096
#define HH 2048
#define LL 4
#define MROWS 16384
#define N3H 6144
#define KDIM 2048

// GEMM tiling: CTA 128x128, BK=16, 2-stage cp.async, 8 warps (4x2), warp 32x64
// 2-pass split: A = Ah + Al (fp16 hi/lo), B = Bh (single fp16)
#define BKT 16
#define NITER (KDIM / BKT)          // 128
#define TILE_B 4096                 // 128 rows x 32 bytes
#define STAGE_B (3 * TILE_B)        // Ah, Al, Bh = 12 KB

// ---------------- scratch (__device__ globals; referenced ONLY in device code)
__device__ float  g_BCx[(size_t)MROWS * N3H];     // 384 MB fp32
__device__ __half g_xh[(size_t)MROWS * HH];
__device__ __half g_xl[(size_t)MROWS * HH];
__device__ __half g_yh[(size_t)MROWS * HH];
__device__ __half g_yl[(size_t)MROWS * HH];
__device__ __half g_Wint_h[(size_t)N3H * HH];     // W_in^T  [6144][2048] fp16
__device__ __half g_Wot_h[(size_t)HH * HH];       // W_out^T [2048][2048] fp16

// ---------------- PTX helpers (plain sm_103-safe) ----------------------------
__device__ __forceinline__ uint32_t smem_u32(const void* p) {
    uint32_t a;
    asm("{ .reg .u64 t; cvta.to.shared.u64 t, %1; cvt.u32.u64 %0, t; }" : "=r"(a) : "l"(p));
    return a;
}
// swizzle for 32B-row tiles: spread 16B chunks so 8 ldmatrix rows hit 8 slots
#define SWZ32(off) ((off) ^ (((off) >> 3) & 0x10))

#define CP_ASYNC16(dst, src) \
    asm volatile("cp.async.cg.shared.global [%0], [%1], 16;" :: "r"(dst), "l"(src))
#define CP_ASYNC_COMMIT() asm volatile("cp.async.commit_group;")
#define CP_ASYNC_WAIT(n)  asm volatile("cp.async.wait_group %0;" :: "n"(n))

#define LDSM_X4(r0, r1, r2, r3, addr) \
    asm volatile("ldmatrix.sync.aligned.m8n8.x4.shared.b16 {%0,%1,%2,%3}, [%4];" \
        : "=r"(r0), "=r"(r1), "=r"(r2), "=r"(r3) : "r"(addr))

// NOT volatile: pure register computation; ptxas may schedule freely.
#define MMA16816(d, a, b0, b1) \
    asm("mma.sync.aligned.m16n8k16.row.col.f32.f16.f16.f32 " \
        "{%0,%1,%2,%3}, {%4,%5,%6,%7}, {%8,%9}, {%0,%1,%2,%3};" \
        : "+f"((d)[0]), "+f"((d)[1]), "+f"((d)[2]), "+f"((d)[3]) \
        : "r"((a)[0]), "r"((a)[1]), "r"((a)[2]), "r"((a)[3]), "r"(b0), "r"(b1))

// ---------------- prep kernels ----------------------------------------------
__global__ __launch_bounds__(256)
void split_x_kernel(const float* __restrict__ x)
{
    size_t i = ((size_t)blockIdx.x * 256 + threadIdx.x) * 4;
    float4 v = *(const float4*)(x + i);
    float f[4] = {v.x, v.y, v.z, v.w};
    __half h[4], l[4];
    #pragma unroll
    for (int j = 0; j < 4; ++j) {
        h[j] = __float2half(f[j]);
        l[j] = __float2half(f[j] - __half2float(h[j]));
    }
    *(uint2*)(g_xh + i) = *(uint2*)h;
    *(uint2*)(g_xl + i) = *(uint2*)l;
}

// transpose: in fp32 [R][C] -> (device-global) fp16 [C][R] (hi only)
__global__ __launch_bounds__(256)
void transpose_h_kernel(const float* __restrict__ in, int wsel, int R, int C)
{
    __half* __restrict__ oh = wsel ? g_Wot_h : g_Wint_h;

    __shared__ float tile[32][33];
    int tx = threadIdx.x, ty = threadIdx.y;
    int x = blockIdx.x * 32 + tx;
    int y0 = blockIdx.y * 32;
    #pragma unroll
    for (int j = ty; j < 32; j += 8)
        tile[j][tx] = in[(size_t)(y0 + j) * C + x];
    __syncthreads();
    int ox = y0 + tx;
    int oy0 = blockIdx.x * 32;
    #pragma unroll
    for (int j = ty; j < 32; j += 8)
        oh[(size_t)(oy0 + j) * R + ox] = __float2half(tile[tx][j]);
}

// ---------------- 2-pass split-precision fp16 mma.sync GEMM -----------------
__device__ __forceinline__ void load_stage16(
    char* sbase, int k0, int bm, int bn,
    const __half* __restrict__ Ah, const __half* __restrict__ Al,
    const __half* __restrict__ Bh, int tid)
{
    const __half* srcs[3] = {Ah, Al, Bh};
    const int r = tid >> 1;          // row 0..127
    const int ch = tid & 1;          // 16B chunk 0..1
    #pragma unroll
    for (int sub = 0; sub < 3; ++sub) {
        const int rowbase = (sub < 2) ? bm : bn;
        uint32_t dst = smem_u32(sbase + sub * TILE_B);
        const __half* src = srcs[sub] + (size_t)(rowbase + r) * KDIM + k0 + ch * 8;
        CP_ASYNC16(dst + SWZ32(r * 32 + ch * 16), src);
    }
    CP_ASYNC_COMMIT();
}

// gsel: 0 -> A=g_xh/g_xl, B=g_Wint_h, C=g_BCx (Cw=N3H)
//       1 -> A=g_yh/g_yl, B=g_Wot_h,  C=Cout  (Cw=HH)
__global__ __launch_bounds__(256, 1)
void gemm_mma_kernel(int gsel, float* __restrict__ Cout)
{
    const __half* __restrict__ Ah = gsel ? g_yh : g_xh;
    const __half* __restrict__ Al = gsel ? g_yl : g_xl;
    const __half* __restrict__ Bh = gsel ? g_Wot_h : g_Wint_h;
    float* __restrict__ C  = gsel ? Cout : g_BCx;
    const int Cw = gsel ? HH : N3H;

    __shared__ __align__(1024) char smem[2 * STAGE_B];   // 24 KB static
    const int tid = threadIdx.x;
    const int wid = tid >> 5;
    const int lid = tid & 31;
    const int wm = wid & 3;           // 4 warps in M -> 32 rows each
    const int wn = wid >> 2;          // 2 warps in N -> 64 cols each
    const int bm = blockIdx.y * 128;
    const int bn = blockIdx.x * 128;

    float acc[2][8][4];
    #pragma unroll
    for (int t = 0; t < 2; ++t)
        #pragma unroll
        for (int j = 0; j < 8; ++j)
            #pragma unroll
            for (int e = 0; e < 4; ++e) acc[t][j][e] = 0.f;

    // ldmatrix lane address components (tile-local)
    const int a_row = (lid & 15);
    const int a_kb  = (lid & 16) ? 16 : 0;
    const int b_row = (lid & 7) + ((lid & 16) ? 8 : 0);
    const int b_kb  = (lid & 8) ? 16 : 0;

    // prologue: 2 stages in flight
    load_stage16(smem,           0,   bm, bn, Ah, Al, Bh, tid);
    load_stage16(smem + STAGE_B, BKT, bm, bn, Ah, Al, Bh, tid);

    for (int i = 0; i < NITER; ++i) {
        if (i + 2 < NITER) { CP_ASYNC_WAIT(1); } else { CP_ASYNC_WAIT(0); }
        __syncthreads();

        char* sbase = smem + (i & 1) * STAGE_B;
        const uint32_t tAh = smem_u32(sbase);
        const uint32_t tAl = tAh + TILE_B;
        const uint32_t tBh = tAh + 2 * TILE_B;

        uint32_t ah[2][4], al[2][4], bh[4][4];
        #pragma unroll
        for (int t = 0; t < 2; ++t) {
            int row = wm * 32 + t * 16 + a_row;
            LDSM_X4(ah[t][0], ah[t][1], ah[t][2], ah[t][3], tAh + SWZ32(row * 32 + a_kb));
            LDSM_X4(al[t][0], al[t][1], al[t][2], al[t][3], tAl + SWZ32(row * 32 + a_kb));
        }
        #pragma unroll
        for (int g = 0; g < 4; ++g) {
            int row = wn * 64 + g * 16 + b_row;
            LDSM_X4(bh[g][0], bh[g][1], bh[g][2], bh[g][3], tBh + SWZ32(row * 32 + b_kb));
        }

        // pass-major: 16 independent accumulators per pass
        #pragma unroll
        for (int t = 0; t < 2; ++t)      // pass 1: Ah * Bh
            #pragma unroll
            for (int g = 0; g < 4; ++g) {
                MMA16816(acc[t][2 * g],     ah[t], bh[g][0], bh[g][1]);
                MMA16816(acc[t][2 * g + 1], ah[t], bh[g][2], bh[g][3]);
            }
        #pragma unroll
        for (int t = 0; t < 2; ++t)      // pass 2: Al * Bh
            #pragma unroll
            for (int g = 0; g < 4; ++g) {
                MMA16816(acc[t][2 * g],     al[t], bh[g][0], bh[g][1]);
                MMA16816(acc[t][2 * g + 1], al[t], bh[g][2], bh[g][3]);
            }

        __syncthreads();
        if (i + 2 < NITER)
            load_stage16(smem + (i & 1) * STAGE_B, (i + 2) * BKT, bm, bn, Ah, Al, Bh, tid);
    }

    // epilogue: fp32 accum -> C
    const int r0 = bm + wm * 32 + (lid >> 2);
    const int cb = bn + wn * 64 + (lid & 3) * 2;
    #pragma unroll
    for (int t = 0; t < 2; ++t)
        #pragma unroll
        for (int j = 0; j < 8; ++j) {
            float2 v0 = make_float2(acc[t][j][0], acc[t][j][1]);
            float2 v1 = make_float2(acc[t][j][2], acc[t][j][3]);
            *(float2*)(C + (size_t)(r0 + t * 16)     * Cw + cb + j * 8) = v0;
            *(float2*)(C + (size_t)(r0 + t * 16 + 8) * Cw + cb + j * 8) = v1;
        }
}

// ---------------- fused gate + mask + causal conv + Cg gate -----------------
#define CONV_CHUNK 128

__global__ __launch_bounds__(256)
void conv_kernel(const int* __restrict__ mask, const float* __restrict__ conv_w)
{
    const int h  = blockIdx.x * 256 + threadIdx.x;
    const int b  = blockIdx.z;
    const int t0 = blockIdx.y * CONV_CHUNK;

    const float cw0 = conv_w[h * LL + 0];
    const float cw1 = conv_w[h * LL + 1];
    const float cw2 = conv_w[h * LL + 2];
    const float cw3 = conv_w[h * LL + 3];

    float p1 = 0.f, p2 = 0.f, p3 = 0.f;
    #pragma unroll
    for (int d = 3; d >= 1; --d) {
        int t = t0 - d;
        float bx = 0.f;
        if (t >= 0 && mask[b * TT + t] != 0) {
            size_t base = ((size_t)(b * TT + t)) * N3H;
            bx = g_BCx[base + h] * g_BCx[base + 2 * HH + h];
        }
        p3 = p2; p2 = p1; p1 = bx;
    }

    for (int t = t0; t < t0 + CONV_CHUNK; ++t) {
        size_t base = ((size_t)(b * TT + t)) * N3H;
        float Bg = g_BCx[base + h];
        float Cg = g_BCx[base + HH + h];
        float xg = g_BCx[base + 2 * HH + h];
        float bx = (mask[b * TT + t] != 0) ? (Bg * xg) : 0.f;
        float conv = cw0 * p3 + cw1 * p2 + cw2 * p1 + cw3 * bx;
        float y = Cg * conv;
        size_t o = ((size_t)(b * TT + t)) * HH + h;
        __half hh = __float2half(y);
        g_yh[o] = hh;
        g_yl[o] = __float2half(y - __half2float(hh));
        p3 = p2; p2 = p1; p1 = bx;
    }
}

// ---------------- launch -----------------------------------------------------
extern "C" void kernel_launch(void* const* d_in, const int* in_sizes, int n_in,
                              void* d_out, int out_size)
{
    const float* x      = (const float*)d_in[0];
    const int*   mask   = (const int*)d_in[1];    // bool widened to int32
    const float* W_in   = (const float*)d_in[2];
    const float* conv_w = (const float*)d_in[3];
    const float* W_out  = (const float*)d_in[4];
    float*       out    = (float*)d_out;

    // prep: split x, transpose weights to fp16 (globals selected device-side)
    split_x_kernel<<<(size_t)MROWS * HH / (256 * 4), 256>>>(x);
    transpose_h_kernel<<<dim3(N3H / 32, HH / 32), dim3(32, 8)>>>(W_in, 0, HH, N3H);
    transpose_h_kernel<<<dim3(HH / 32, HH / 32), dim3(32, 8)>>>(W_out, 1, HH, HH);

    // GEMM1: BCx = x @ W_in   (16384x2048 @ 2048x6144)
    gemm_mma_kernel<<<dim3(N3H / 128, MROWS / 128), 256>>>(0, nullptr);

    // gate + conv + gate -> y (split fp16)
    conv_kernel<<<dim3(HH / 256, TT / CONV_CHUNK, BB), 256>>>(mask, conv_w);

    // GEMM2: out = y @ W_out  (16384x2048 @ 2048x2048)
    gemm_mma_kernel<<<dim3(HH / 128, MROWS / 128), 256>>>(1, out);
}

// round 11
// speedup vs baseline: 3.0265x; 1.4220x over previous
#include <cuda_runtime.h>
#include <cuda_fp16.h>
#include <cstdint>

// Problem dims (fixed)
#define BB 4
#define TT 4096
#define HH 2048
#define LL 4
#define MROWS 16384
#define N3H 6144
#define KDIM 2048

// GEMM tiling: CTA 128x128, BK=16, 3-stage cp.async, 8 warps (4x2), warp 32x64
#define BKT 16
#define NITER (KDIM / BKT)          // 128
#define TILE_B 4096                 // 128 rows x 32 bytes
#define NSTAGE 3

// ---------------- scratch (__device__ globals; referenced ONLY in device code)
__device__ float  g_BCx[(size_t)MROWS * N3H];     // 384 MB fp32
__device__ __half g_xh[(size_t)MROWS * HH];
__device__ __half g_yh[(size_t)MROWS * HH];
__device__ __half g_yl[(size_t)MROWS * HH];
__device__ __half g_Wint_h[(size_t)N3H * HH];     // W_in^T  [6144][2048] fp16
__device__ __half g_Wot_h[(size_t)HH * HH];       // W_out^T [2048][2048] fp16

// ---------------- PTX helpers (plain sm_103-safe) ----------------------------
__device__ __forceinline__ uint32_t smem_u32(const void* p) {
    uint32_t a;
    asm("{ .reg .u64 t; cvta.to.shared.u64 t, %1; cvt.u32.u64 %0, t; }" : "=r"(a) : "l"(p));
    return a;
}
// swizzle for 32B-row tiles: spread 16B chunks so 8 ldmatrix rows hit 8 slots
#define SWZ32(off) ((off) ^ (((off) >> 3) & 0x10))

#define CP_ASYNC16(dst, src) \
    asm volatile("cp.async.cg.shared.global [%0], [%1], 16;" :: "r"(dst), "l"(src))
#define CP_ASYNC_COMMIT() asm volatile("cp.async.commit_group;")
#define CP_ASYNC_WAIT(n)  asm volatile("cp.async.wait_group %0;" :: "n"(n))

#define LDSM_X4(r0, r1, r2, r3, addr) \
    asm volatile("ldmatrix.sync.aligned.m8n8.x4.shared.b16 {%0,%1,%2,%3}, [%4];" \
        : "=r"(r0), "=r"(r1), "=r"(r2), "=r"(r3) : "r"(addr))

// NOT volatile: pure register computation; ptxas may schedule freely.
#define MMA16816(d, a, b0, b1) \
    asm("mma.sync.aligned.m16n8k16.row.col.f32.f16.f16.f32 " \
        "{%0,%1,%2,%3}, {%4,%5,%6,%7}, {%8,%9}, {%0,%1,%2,%3};" \
        : "+f"((d)[0]), "+f"((d)[1]), "+f"((d)[2]), "+f"((d)[3]) \
        : "r"((a)[0]), "r"((a)[1]), "r"((a)[2]), "r"((a)[3]), "r"(b0), "r"(b1))

// ---------------- prep kernels ----------------------------------------------
__global__ __launch_bounds__(256)
void convert_x_kernel(const float* __restrict__ x)   // hi only
{
    size_t i = ((size_t)blockIdx.x * 256 + threadIdx.x) * 4;
    float4 v = *(const float4*)(x + i);
    __half h[4] = {__float2half(v.x), __float2half(v.y),
                   __float2half(v.z), __float2half(v.w)};
    *(uint2*)(g_xh + i) = *(uint2*)h;
}

// transpose: in fp32 [R][C] -> (device-global) fp16 [C][R]
__global__ __launch_bounds__(256)
void transpose_h_kernel(const float* __restrict__ in, int wsel, int R, int C)
{
    __half* __restrict__ oh = wsel ? g_Wot_h : g_Wint_h;

    __shared__ float tile[32][33];
    int tx = threadIdx.x, ty = threadIdx.y;
    int x = blockIdx.x * 32 + tx;
    int y0 = blockIdx.y * 32;
    #pragma unroll
    for (int j = ty; j < 32; j += 8)
        tile[j][tx] = in[(size_t)(y0 + j) * C + x];
    __syncthreads();
    int ox = y0 + tx;
    int oy0 = blockIdx.x * 32;
    #pragma unroll
    for (int j = ty; j < 32; j += 8)
        oh[(size_t)(oy0 + j) * R + ox] = __float2half(tile[tx][j]);
}

// ---------------- split-precision fp16 mma.sync GEMM (templated passes) -----
// GSEL 0: C=g_BCx (Cw=N3H), A={g_xh}, 1 pass.   stage = [Ah][Bh] 8 KB
// GSEL 1: C=Cout  (Cw=HH),  A={g_yh,g_yl}, 2 p. stage = [Ah][Al][Bh] 12 KB
template<int GSEL>
__global__ __launch_bounds__(256, 2)
void gemm_mma_kernel(float* __restrict__ Cout)
{
    constexpr int NPASS = GSEL ? 2 : 1;
    constexpr int NTILE = NPASS + 1;
    constexpr int STG_B = NTILE * TILE_B;

    const __half* __restrict__ Ah = GSEL ? g_yh : g_xh;
    const __half* __restrict__ Al = GSEL ? g_yl : g_xh;   // unused when NPASS==1
    const __half* __restrict__ Bh = GSEL ? g_Wot_h : g_Wint_h;
    float* __restrict__ C  = GSEL ? Cout : g_BCx;
    const int Cw = GSEL ? HH : N3H;

    __shared__ __align__(1024) char smem[NSTAGE * STG_B];
    const int tid = threadIdx.x;
    const int wid = tid >> 5;
    const int lid = tid & 31;
    const int wm = wid & 3;           // 4 warps in M -> 32 rows each
    const int wn = wid >> 2;          // 2 warps in N -> 64 cols each
    const int bm = blockIdx.y * 128;
    const int bn = blockIdx.x * 128;

    float acc[2][8][4];
    #pragma unroll
    for (int t = 0; t < 2; ++t)
        #pragma unroll
        for (int j = 0; j < 8; ++j)
            #pragma unroll
            for (int e = 0; e < 4; ++e) acc[t][j][e] = 0.f;

    const int a_row = (lid & 15);
    const int a_kb  = (lid & 16) ? 16 : 0;
    const int b_row = (lid & 7) + ((lid & 16) ? 8 : 0);
    const int b_kb  = (lid & 8) ? 16 : 0;

    // loader lambda: one stage (NTILE tiles), 2 chunks/row
    const int lr = tid >> 1, lch = tid & 1;
    auto load_stage = [&](char* sbase, int k0) {
        const __half* srcs[3] = {Ah, NPASS == 2 ? Al : Bh, Bh};
        #pragma unroll
        for (int sub = 0; sub < NTILE; ++sub) {
            const int rowbase = (sub < NPASS) ? bm : bn;   // A tiles then B tile
            uint32_t dst = smem_u32(sbase + sub * TILE_B);
            const __half* src = ((sub == NTILE - 1) ? Bh : (sub == 0 ? Ah : Al))
                                + (size_t)(rowbase + lr) * KDIM + k0 + lch * 8;
            (void)srcs;
            CP_ASYNC16(dst + SWZ32(lr * 32 + lch * 16), src);
        }
        CP_ASYNC_COMMIT();
    };

    // prologue: 2 stages in flight
    load_stage(smem,         0);
    load_stage(smem + STG_B, BKT);

    for (int i = 0; i < NITER; ++i) {
        if (i + 1 < NITER) { CP_ASYNC_WAIT(1); } else { CP_ASYNC_WAIT(0); }
        __syncthreads();

        int cur = i % NSTAGE;
        char* sbase = smem + cur * STG_B;
        const uint32_t tAh = smem_u32(sbase);
        const uint32_t tAl = tAh + TILE_B;                  // valid when NPASS==2
        const uint32_t tBh = tAh + (NTILE - 1) * TILE_B;

        uint32_t ah[2][4], al[2][4], bh[4][4];
        #pragma unroll
        for (int t = 0; t < 2; ++t) {
            int row = wm * 32 + t * 16 + a_row;
            LDSM_X4(ah[t][0], ah[t][1], ah[t][2], ah[t][3], tAh + SWZ32(row * 32 + a_kb));
            if (NPASS == 2)
                LDSM_X4(al[t][0], al[t][1], al[t][2], al[t][3], tAl + SWZ32(row * 32 + a_kb));
        }
        #pragma unroll
        for (int g = 0; g < 4; ++g) {
            int row = wn * 64 + g * 16 + b_row;
            LDSM_X4(bh[g][0], bh[g][1], bh[g][2], bh[g][3], tBh + SWZ32(row * 32 + b_kb));
        }

        #pragma unroll
        for (int t = 0; t < 2; ++t)      // pass 1: Ah * Bh
            #pragma unroll
            for (int g = 0; g < 4; ++g) {
                MMA16816(acc[t][2 * g],     ah[t], bh[g][0], bh[g][1]);
                MMA16816(acc[t][2 * g + 1], ah[t], bh[g][2], bh[g][3]);
            }
        if (NPASS == 2) {
            #pragma unroll
            for (int t = 0; t < 2; ++t)  // pass 2: Al * Bh
                #pragma unroll
                for (int g = 0; g < 4; ++g) {
                    MMA16816(acc[t][2 * g],     al[t], bh[g][0], bh[g][1]);
                    MMA16816(acc[t][2 * g + 1], al[t], bh[g][2], bh[g][3]);
                }
        }

        // load stage i+2 into (cur+2)%3: its readers (iter i-1) passed the
        // barrier at the top of this iteration -> safe without a 2nd barrier.
        if (i + 2 < NITER) {
            int nxt = cur + 2; if (nxt >= NSTAGE) nxt -= NSTAGE;
            load_stage(smem + nxt * STG_B, (i + 2) * BKT);
        }
    }

    // epilogue: fp32 accum -> C
    const int r0 = bm + wm * 32 + (lid >> 2);
    const int cb = bn + wn * 64 + (lid & 3) * 2;
    #pragma unroll
    for (int t = 0; t < 2; ++t)
        #pragma unroll
        for (int j = 0; j < 8; ++j) {
            float2 v0 = make_float2(acc[t][j][0], acc[t][j][1]);
            float2 v1 = make_float2(acc[t][j][2], acc[t][j][3]);
            *(float2*)(C + (size_t)(r0 + t * 16)     * Cw + cb + j * 8) = v0;
            *(float2*)(C + (size_t)(r0 + t * 16 + 8) * Cw + cb + j * 8) = v1;
        }
}

// ---------------- fused gate + mask + causal conv + Cg gate -----------------
#define CONV_CHUNK 128

__global__ __launch_bounds__(256)
void conv_kernel(const int* __restrict__ mask, const float* __restrict__ conv_w)
{
    const int h  = blockIdx.x * 256 + threadIdx.x;
    const int b  = blockIdx.z;
    const int t0 = blockIdx.y * CONV_CHUNK;

    const float cw0 = conv_w[h * LL + 0];
    const float cw1 = conv_w[h * LL + 1];
    const float cw2 = conv_w[h * LL + 2];
    const float cw3 = conv_w[h * LL + 3];

    float p1 = 0.f, p2 = 0.f, p3 = 0.f;
    #pragma unroll
    for (int d = 3; d >= 1; --d) {
        int t = t0 - d;
        float bx = 0.f;
        if (t >= 0 && mask[b * TT + t] != 0) {
            size_t base = ((size_t)(b * TT + t)) * N3H;
            bx = g_BCx[base + h] * g_BCx[base + 2 * HH + h];
        }
        p3 = p2; p2 = p1; p1 = bx;
    }

    for (int t = t0; t < t0 + CONV_CHUNK; ++t) {
        size_t base = ((size_t)(b * TT + t)) * N3H;
        float Bg = g_BCx[base + h];
        float Cg = g_BCx[base + HH + h];
        float xg = g_BCx[base + 2 * HH + h];
        float bx = (mask[b * TT + t] != 0) ? (Bg * xg) : 0.f;
        float conv = cw0 * p3 + cw1 * p2 + cw2 * p1 + cw3 * bx;
        float y = Cg * conv;
        size_t o = ((size_t)(b * TT + t)) * HH + h;
        __half hh = __float2half(y);
        g_yh[o] = hh;
        g_yl[o] = __float2half(y - __half2float(hh));
        p3 = p2; p2 = p1; p1 = bx;
    }
}

// ---------------- launch -----------------------------------------------------
extern "C" void kernel_launch(void* const* d_in, const int* in_sizes, int n_in,
                              void* d_out, int out_size)
{
    const float* x      = (const float*)d_in[0];
    const int*   mask   = (const int*)d_in[1];    // bool widened to int32
    const float* W_in   = (const float*)d_in[2];
    const float* conv_w = (const float*)d_in[3];
    const float* W_out  = (const float*)d_in[4];
    float*       out    = (float*)d_out;

    // prep: convert x to fp16 hi, transpose weights to fp16
    convert_x_kernel<<<(size_t)MROWS * HH / (256 * 4), 256>>>(x);
    transpose_h_kernel<<<dim3(N3H / 32, HH / 32), dim3(32, 8)>>>(W_in, 0, HH, N3H);
    transpose_h_kernel<<<dim3(HH / 32, HH / 32), dim3(32, 8)>>>(W_out, 1, HH, HH);

    // GEMM1 (single-pass): BCx = x @ W_in   (16384x2048 @ 2048x6144)
    gemm_mma_kernel<0><<<dim3(N3H / 128, MROWS / 128), 256>>>(nullptr);

    // gate + conv + gate -> y (split fp16)
    conv_kernel<<<dim3(HH / 256, TT / CONV_CHUNK, BB), 256>>>(mask, conv_w);

    // GEMM2 (2-pass): out = y @ W_out  (16384x2048 @ 2048x2048)
    gemm_mma_kernel<1><<<dim3(HH / 128, MROWS / 128), 256>>>(out);
}

// round 12
// speedup vs baseline: 3.5442x; 1.1711x over previous
#include <cuda_runtime.h>
#include <cuda_fp16.h>
#include <cstdint>

// Problem dims (fixed)
#define BB 4
#define TT 4096
#define HH 2048
#define LL 4
#define MROWS 16384
#define N3H 6144
#define KDIM 2048

#define NSTAGE 3

// ---------------- scratch (__device__ globals; referenced ONLY in device code)
__device__ float  g_BCx[(size_t)MROWS * N3H];     // 384 MB fp32
__device__ __half g_xh[(size_t)MROWS * HH];
__device__ __half g_yh[(size_t)MROWS * HH];
__device__ __half g_yl[(size_t)MROWS * HH];
__device__ __half g_Wint_h[(size_t)N3H * HH];     // W_in^T  [6144][2048] fp16
__device__ __half g_Wot_h[(size_t)HH * HH];       // W_out^T [2048][2048] fp16

// ---------------- PTX helpers (plain sm_103-safe) ----------------------------
__device__ __forceinline__ uint32_t smem_u32(const void* p) {
    uint32_t a;
    asm("{ .reg .u64 t; cvta.to.shared.u64 t, %1; cvt.u32.u64 %0, t; }" : "=r"(a) : "l"(p));
    return a;
}
// swizzles: 32B rows (2 chunks) and 64B rows (4 chunks), conflict-free for
// 8-row ldmatrix access groups.
__device__ __forceinline__ uint32_t swz(uint32_t off, int rowb) {
    return (rowb == 64) ? (off ^ ((off >> 3) & 0x30))
                        : (off ^ ((off >> 3) & 0x10));
}

#define CP_ASYNC16(dst, src) \
    asm volatile("cp.async.cg.shared.global [%0], [%1], 16;" :: "r"(dst), "l"(src))
#define CP_ASYNC_COMMIT() asm volatile("cp.async.commit_group;")
#define CP_ASYNC_WAIT(n)  asm volatile("cp.async.wait_group %0;" :: "n"(n))

#define LDSM_X4(r0, r1, r2, r3, addr) \
    asm volatile("ldmatrix.sync.aligned.m8n8.x4.shared.b16 {%0,%1,%2,%3}, [%4];" \
        : "=r"(r0), "=r"(r1), "=r"(r2), "=r"(r3) : "r"(addr))

// NOT volatile: pure register computation; ptxas may schedule freely.
#define MMA16816(d, a, b0, b1) \
    asm("mma.sync.aligned.m16n8k16.row.col.f32.f16.f16.f32 " \
        "{%0,%1,%2,%3}, {%4,%5,%6,%7}, {%8,%9}, {%0,%1,%2,%3};" \
        : "+f"((d)[0]), "+f"((d)[1]), "+f"((d)[2]), "+f"((d)[3]) \
        : "r"((a)[0]), "r"((a)[1]), "r"((a)[2]), "r"((a)[3]), "r"(b0), "r"(b1))

// ---------------- prep kernels ----------------------------------------------
__global__ __launch_bounds__(256)
void convert_x_kernel(const float* __restrict__ x)   // hi only
{
    size_t i = ((size_t)blockIdx.x * 256 + threadIdx.x) * 4;
    float4 v = *(const float4*)(x + i);
    __half h[4] = {__float2half(v.x), __float2half(v.y),
                   __float2half(v.z), __float2half(v.w)};
    *(uint2*)(g_xh + i) = *(uint2*)h;
}

// transpose: in fp32 [R][C] -> (device-global) fp16 [C][R]
__global__ __launch_bounds__(256)
void transpose_h_kernel(const float* __restrict__ in, int wsel, int R, int C)
{
    __half* __restrict__ oh = wsel ? g_Wot_h : g_Wint_h;

    __shared__ float tile[32][33];
    int tx = threadIdx.x, ty = threadIdx.y;
    int x = blockIdx.x * 32 + tx;
    int y0 = blockIdx.y * 32;
    #pragma unroll
    for (int j = ty; j < 32; j += 8)
        tile[j][tx] = in[(size_t)(y0 + j) * C + x];
    __syncthreads();
    int ox = y0 + tx;
    int oy0 = blockIdx.x * 32;
    #pragma unroll
    for (int j = ty; j < 32; j += 8)
        oh[(size_t)(oy0 + j) * R + ox] = __float2half(tile[tx][j]);
}

// ---------------- split-precision fp16 mma.sync GEMM (templated) ------------
// GSEL 0: C=g_BCx (Cw=N3H), A={g_xh}, 1 pass, BK=32 (64B rows), stage 16 KB
// GSEL 1: C=Cout  (Cw=HH),  A={g_yh,g_yl}, 2 pass, BK=16 (32B rows), stage 12 KB
template<int GSEL>
__global__ __launch_bounds__(256, 2)
void gemm_mma_kernel(float* __restrict__ Cout)
{
    constexpr int NPASS = GSEL ? 2 : 1;
    constexpr int NTILE = NPASS + 1;
    constexpr int ROWB  = GSEL ? 32 : 64;        // bytes per tile row
    constexpr int KCH   = ROWB / 32;             // k16-chunks per iter (1 or 2)
    constexpr int NITER = KDIM / (KCH * 16);
    constexpr int TILEB = 128 * ROWB;
    constexpr int STG_B = NTILE * TILEB;
    constexpr int CPT   = NTILE * 128 * (ROWB / 16) / 256;  // cp.async per thread

    const __half* __restrict__ Ah = GSEL ? g_yh : g_xh;
    const __half* __restrict__ Al = GSEL ? g_yl : g_xh;   // unused when NPASS==1
    const __half* __restrict__ Bh = GSEL ? g_Wot_h : g_Wint_h;
    float* __restrict__ C  = GSEL ? Cout : g_BCx;
    const int Cw = GSEL ? HH : N3H;

    __shared__ __align__(1024) char smem[NSTAGE * STG_B];
    const int tid = threadIdx.x;
    const int wid = tid >> 5;
    const int lid = tid & 31;
    const int wm = wid & 3;           // 4 warps in M -> 32 rows each
    const int wn = wid >> 2;          // 2 warps in N -> 64 cols each
    const int bm = blockIdx.y * 128;
    const int bn = blockIdx.x * 128;

    float acc[2][8][4];
    #pragma unroll
    for (int t = 0; t < 2; ++t)
        #pragma unroll
        for (int j = 0; j < 8; ++j)
            #pragma unroll
            for (int e = 0; e < 4; ++e) acc[t][j][e] = 0.f;

    const int a_row = (lid & 15);
    const int a_kb  = (lid & 16) ? 16 : 0;
    const int b_row = (lid & 7) + ((lid & 16) ? 8 : 0);
    const int b_kb  = (lid & 8) ? 16 : 0;

    // loader: one stage (NTILE tiles of 128 x ROWB), CPT chunks per thread
    auto load_stage = [&](char* sbase, int k0) {
        constexpr int CH_PER_ROW  = ROWB / 16;
        constexpr int CH_PER_TILE = 128 * CH_PER_ROW;
        #pragma unroll
        for (int j = 0; j < CPT; ++j) {
            int c    = tid + j * 256;
            int sub  = c / CH_PER_TILE;
            int cc   = c % CH_PER_TILE;
            int r    = cc / CH_PER_ROW;
            int ch   = cc % CH_PER_ROW;
            const int rowbase = (sub < NPASS) ? bm : bn;
            const __half* src = ((sub == NTILE - 1) ? Bh : (sub == 0 ? Ah : Al))
                                + (size_t)(rowbase + r) * KDIM + k0 + ch * 8;
            uint32_t dst = smem_u32(sbase + sub * TILEB);
            CP_ASYNC16(dst + swz(r * ROWB + ch * 16, ROWB), src);
        }
        CP_ASYNC_COMMIT();
    };

    // prologue: 2 stages in flight
    load_stage(smem,         0);
    load_stage(smem + STG_B, KCH * 16);

    int cur = 0;
    for (int i = 0; i < NITER; ++i) {
        if (i + 1 < NITER) { CP_ASYNC_WAIT(1); } else { CP_ASYNC_WAIT(0); }
        __syncthreads();

        char* sbase = smem + cur * STG_B;
        const uint32_t tAh = smem_u32(sbase);
        const uint32_t tAl = tAh + TILEB;                 // valid when NPASS==2
        const uint32_t tBh = tAh + (NTILE - 1) * TILEB;

        #pragma unroll
        for (int kk = 0; kk < KCH; ++kk) {
            const int kb = kk * 32;
            uint32_t ah[2][4], al[2][4], bh[4][4];
            #pragma unroll
            for (int t = 0; t < 2; ++t) {
                int row = wm * 32 + t * 16 + a_row;
                LDSM_X4(ah[t][0], ah[t][1], ah[t][2], ah[t][3],
                        tAh + swz(row * ROWB + kb + a_kb, ROWB));
                if (NPASS == 2)
                    LDSM_X4(al[t][0], al[t][1], al[t][2], al[t][3],
                            tAl + swz(row * ROWB + kb + a_kb, ROWB));
            }
            #pragma unroll
            for (int g = 0; g < 4; ++g) {
                int row = wn * 64 + g * 16 + b_row;
                LDSM_X4(bh[g][0], bh[g][1], bh[g][2], bh[g][3],
                        tBh + swz(row * ROWB + kb + b_kb, ROWB));
            }

            #pragma unroll
            for (int t = 0; t < 2; ++t)      // pass 1: Ah * Bh
                #pragma unroll
                for (int g = 0; g < 4; ++g) {
                    MMA16816(acc[t][2 * g],     ah[t], bh[g][0], bh[g][1]);
                    MMA16816(acc[t][2 * g + 1], ah[t], bh[g][2], bh[g][3]);
                }
            if (NPASS == 2) {
                #pragma unroll
                for (int t = 0; t < 2; ++t)  // pass 2: Al * Bh
                    #pragma unroll
                    for (int g = 0; g < 4; ++g) {
                        MMA16816(acc[t][2 * g],     al[t], bh[g][0], bh[g][1]);
                        MMA16816(acc[t][2 * g + 1], al[t], bh[g][2], bh[g][3]);
                    }
            }
        }

        // load stage i+2 into (cur+2)%NSTAGE: its readers (iter i-1) passed
        // the barrier at the top of this iteration -> safe with one barrier.
        if (i + 2 < NITER) {
            int nxt = cur + 2; if (nxt >= NSTAGE) nxt -= NSTAGE;
            load_stage(smem + nxt * STG_B, (i + 2) * KCH * 16);
        }
        if (++cur == NSTAGE) cur = 0;
    }

    // epilogue: fp32 accum -> C
    const int r0 = bm + wm * 32 + (lid >> 2);
    const int cb = bn + wn * 64 + (lid & 3) * 2;
    #pragma unroll
    for (int t = 0; t < 2; ++t)
        #pragma unroll
        for (int j = 0; j < 8; ++j) {
            float2 v0 = make_float2(acc[t][j][0], acc[t][j][1]);
            float2 v1 = make_float2(acc[t][j][2], acc[t][j][3]);
            *(float2*)(C + (size_t)(r0 + t * 16)     * Cw + cb + j * 8) = v0;
            *(float2*)(C + (size_t)(r0 + t * 16 + 8) * Cw + cb + j * 8) = v1;
        }
}

// ---------------- fused gate + mask + causal conv + Cg gate -----------------
#define CONV_CHUNK 128

__global__ __launch_bounds__(256)
void conv_kernel(const int* __restrict__ mask, const float* __restrict__ conv_w)
{
    const int h  = blockIdx.x * 256 + threadIdx.x;
    const int b  = blockIdx.z;
    const int t0 = blockIdx.y * CONV_CHUNK;

    const float cw0 = conv_w[h * LL + 0];
    const float cw1 = conv_w[h * LL + 1];
    const float cw2 = conv_w[h * LL + 2];
    const float cw3 = conv_w[h * LL + 3];

    float p1 = 0.f, p2 = 0.f, p3 = 0.f;
    #pragma unroll
    for (int d = 3; d >= 1; --d) {
        int t = t0 - d;
        float bx = 0.f;
        if (t >= 0 && mask[b * TT + t] != 0) {
            size_t base = ((size_t)(b * TT + t)) * N3H;
            bx = g_BCx[base + h] * g_BCx[base + 2 * HH + h];
        }
        p3 = p2; p2 = p1; p1 = bx;
    }

    for (int t = t0; t < t0 + CONV_CHUNK; ++t) {
        size_t base = ((size_t)(b * TT + t)) * N3H;
        float Bg = g_BCx[base + h];
        float Cg = g_BCx[base + HH + h];
        float xg = g_BCx[base + 2 * HH + h];
        float bx = (mask[b * TT + t] != 0) ? (Bg * xg) : 0.f;
        float conv = cw0 * p3 + cw1 * p2 + cw2 * p1 + cw3 * bx;
        float y = Cg * conv;
        size_t o = ((size_t)(b * TT + t)) * HH + h;
        __half hh = __float2half(y);
        g_yh[o] = hh;
        g_yl[o] = __float2half(y - __half2float(hh));
        p3 = p2; p2 = p1; p1 = bx;
    }
}

// ---------------- launch -----------------------------------------------------
extern "C" void kernel_launch(void* const* d_in, const int* in_sizes, int n_in,
                              void* d_out, int out_size)
{
    const float* x      = (const float*)d_in[0];
    const int*   mask   = (const int*)d_in[1];    // bool widened to int32
    const float* W_in   = (const float*)d_in[2];
    const float* conv_w = (const float*)d_in[3];
    const float* W_out  = (const float*)d_in[4];
    float*       out    = (float*)d_out;

    // prep: convert x to fp16 hi, transpose weights to fp16
    convert_x_kernel<<<(size_t)MROWS * HH / (256 * 4), 256>>>(x);
    transpose_h_kernel<<<dim3(N3H / 32, HH / 32), dim3(32, 8)>>>(W_in, 0, HH, N3H);
    transpose_h_kernel<<<dim3(HH / 32, HH / 32), dim3(32, 8)>>>(W_out, 1, HH, HH);

    // GEMM1 (single-pass, BK=32): BCx = x @ W_in
    gemm_mma_kernel<0><<<dim3(N3H / 128, MROWS / 128), 256>>>(nullptr);

    // gate + conv + gate -> y (split fp16)
    conv_kernel<<<dim3(HH / 256, TT / CONV_CHUNK, BB), 256>>>(mask, conv_w);

    // GEMM2 (2-pass, BK=16): out = y @ W_out
    gemm_mma_kernel<1><<<dim3(HH / 128, MROWS / 128), 256>>>(out);
}

// round 13
// speedup vs baseline: 4.3809x; 1.2361x over previous
#include <cuda_runtime.h>
#include <cuda_fp16.h>
#include <cstdint>

// Problem dims (fixed)
#define BB 4
#define TT 4096
#define HH 2048
#define LL 4
#define MROWS 16384
#define N3H 6144
#define KDIM 2048

// GEMM tiling: CTA 128x128, BK=32 (64B rows), 3-stage cp.async, 8 warps (4x2),
// warp 32x64, single pass (A fp16, B fp16), fp32 accum.
#define ROWB  64
#define KCH   2                       // k16 chunks per iter
#define NITER (KDIM / 32)             // 64
#define TILEB (128 * ROWB)            // 8 KB
#define STG_B (2 * TILEB)             // A + B = 16 KB
#define NSTAGE 3                      // 48 KB static

// ---------------- scratch (__device__ globals; referenced ONLY in device code)
__device__ float  g_BCx[(size_t)MROWS * N3H];     // 384 MB fp32
__device__ __half g_xh[(size_t)MROWS * HH];
__device__ __half g_yh[(size_t)MROWS * HH];
__device__ __half g_Wint_h[(size_t)N3H * HH];     // W_in^T  [6144][2048] fp16
__device__ __half g_Wot_h[(size_t)HH * HH];       // W_out^T [2048][2048] fp16

// ---------------- PTX helpers (plain sm_103-safe) ----------------------------
__device__ __forceinline__ uint32_t smem_u32(const void* p) {
    uint32_t a;
    asm("{ .reg .u64 t; cvta.to.shared.u64 t, %1; cvt.u32.u64 %0, t; }" : "=r"(a) : "l"(p));
    return a;
}
// 64B-row swizzle: conflict-free for 8-row ldmatrix groups
#define SWZ64(off) ((off) ^ (((off) >> 3) & 0x30))

#define CP_ASYNC16(dst, src) \
    asm volatile("cp.async.cg.shared.global [%0], [%1], 16;" :: "r"(dst), "l"(src))
#define CP_ASYNC_COMMIT() asm volatile("cp.async.commit_group;")
#define CP_ASYNC_WAIT(n)  asm volatile("cp.async.wait_group %0;" :: "n"(n))

#define LDSM_X4(r0, r1, r2, r3, addr) \
    asm volatile("ldmatrix.sync.aligned.m8n8.x4.shared.b16 {%0,%1,%2,%3}, [%4];" \
        : "=r"(r0), "=r"(r1), "=r"(r2), "=r"(r3) : "r"(addr))

// NOT volatile: pure register computation; ptxas may schedule freely.
#define MMA16816(d, a, b0, b1) \
    asm("mma.sync.aligned.m16n8k16.row.col.f32.f16.f16.f32 " \
        "{%0,%1,%2,%3}, {%4,%5,%6,%7}, {%8,%9}, {%0,%1,%2,%3};" \
        : "+f"((d)[0]), "+f"((d)[1]), "+f"((d)[2]), "+f"((d)[3]) \
        : "r"((a)[0]), "r"((a)[1]), "r"((a)[2]), "r"((a)[3]), "r"(b0), "r"(b1))

// ---------------- prep kernels ----------------------------------------------
__global__ __launch_bounds__(256)
void convert_x_kernel(const float* __restrict__ x)
{
    size_t i = ((size_t)blockIdx.x * 256 + threadIdx.x) * 4;
    float4 v = *(const float4*)(x + i);
    __half h[4] = {__float2half(v.x), __float2half(v.y),
                   __float2half(v.z), __float2half(v.w)};
    *(uint2*)(g_xh + i) = *(uint2*)h;
}

// transpose: in fp32 [R][C] -> (device-global) fp16 [C][R]
__global__ __launch_bounds__(256)
void transpose_h_kernel(const float* __restrict__ in, int wsel, int R, int C)
{
    __half* __restrict__ oh = wsel ? g_Wot_h : g_Wint_h;

    __shared__ float tile[32][33];
    int tx = threadIdx.x, ty = threadIdx.y;
    int x = blockIdx.x * 32 + tx;
    int y0 = blockIdx.y * 32;
    #pragma unroll
    for (int j = ty; j < 32; j += 8)
        tile[j][tx] = in[(size_t)(y0 + j) * C + x];
    __syncthreads();
    int ox = y0 + tx;
    int oy0 = blockIdx.x * 32;
    #pragma unroll
    for (int j = ty; j < 32; j += 8)
        oh[(size_t)(oy0 + j) * R + ox] = __float2half(tile[tx][j]);
}

// ---------------- single-pass fp16 mma.sync GEMM -----------------------------
// gsel 0: C = g_BCx = g_xh @ g_Wint_h^T  (Cw = N3H)
// gsel 1: C = Cout  = g_yh @ g_Wot_h^T   (Cw = HH)
__global__ __launch_bounds__(256, 2)
void gemm_mma_kernel(int gsel, float* __restrict__ Cout)
{
    const __half* __restrict__ A = gsel ? g_yh : g_xh;
    const __half* __restrict__ B = gsel ? g_Wot_h : g_Wint_h;
    float* __restrict__ C  = gsel ? Cout : g_BCx;
    const int Cw = gsel ? HH : N3H;

    __shared__ __align__(1024) char smem[NSTAGE * STG_B];
    const int tid = threadIdx.x;
    const int wid = tid >> 5;
    const int lid = tid & 31;
    const int wm = wid & 3;           // 4 warps in M -> 32 rows each
    const int wn = wid >> 2;          // 2 warps in N -> 64 cols each
    const int bm = blockIdx.y * 128;
    const int bn = blockIdx.x * 128;

    float acc[2][8][4];
    #pragma unroll
    for (int t = 0; t < 2; ++t)
        #pragma unroll
        for (int j = 0; j < 8; ++j)
            #pragma unroll
            for (int e = 0; e < 4; ++e) acc[t][j][e] = 0.f;

    const int a_row = (lid & 15);
    const int a_kb  = (lid & 16) ? 16 : 0;
    const int b_row = (lid & 7) + ((lid & 16) ? 8 : 0);
    const int b_kb  = (lid & 8) ? 16 : 0;

    // loader: one stage = A tile + B tile, 128 rows x 4 chunks each
    // 1024 chunks total -> 4 per thread
    auto load_stage = [&](char* sbase, int k0) {
        #pragma unroll
        for (int j = 0; j < 4; ++j) {
            int c   = tid + j * 256;       // 0..1023
            int sub = c >> 9;              // 0 = A, 1 = B
            int cc  = c & 511;
            int r   = cc >> 2, ch = cc & 3;
            const int rowbase = sub ? bn : bm;
            const __half* src = (sub ? B : A)
                                + (size_t)(rowbase + r) * KDIM + k0 + ch * 8;
            uint32_t dst = smem_u32(sbase + sub * TILEB);
            CP_ASYNC16(dst + SWZ64(r * ROWB + ch * 16), src);
        }
        CP_ASYNC_COMMIT();
    };

    // prologue: 2 stages in flight
    load_stage(smem,         0);
    load_stage(smem + STG_B, 32);

    int cur = 0;
    for (int i = 0; i < NITER; ++i) {
        if (i + 1 < NITER) { CP_ASYNC_WAIT(1); } else { CP_ASYNC_WAIT(0); }
        __syncthreads();

        char* sbase = smem + cur * STG_B;
        const uint32_t tA = smem_u32(sbase);
        const uint32_t tB = tA + TILEB;

        #pragma unroll
        for (int kk = 0; kk < KCH; ++kk) {
            const int kb = kk * 32;
            uint32_t av[2][4], bv[4][4];
            #pragma unroll
            for (int t = 0; t < 2; ++t) {
                int row = wm * 32 + t * 16 + a_row;
                LDSM_X4(av[t][0], av[t][1], av[t][2], av[t][3],
                        tA + SWZ64(row * ROWB + kb + a_kb));
            }
            #pragma unroll
            for (int g = 0; g < 4; ++g) {
                int row = wn * 64 + g * 16 + b_row;
                LDSM_X4(bv[g][0], bv[g][1], bv[g][2], bv[g][3],
                        tB + SWZ64(row * ROWB + kb + b_kb));
            }
            #pragma unroll
            for (int t = 0; t < 2; ++t)
                #pragma unroll
                for (int g = 0; g < 4; ++g) {
                    MMA16816(acc[t][2 * g],     av[t], bv[g][0], bv[g][1]);
                    MMA16816(acc[t][2 * g + 1], av[t], bv[g][2], bv[g][3]);
                }
        }

        // load stage i+2 into (cur+2)%NSTAGE: its readers (iter i-1) passed
        // the barrier at the top of this iteration -> safe with one barrier.
        if (i + 2 < NITER) {
            int nxt = cur + 2; if (nxt >= NSTAGE) nxt -= NSTAGE;
            load_stage(smem + nxt * STG_B, (i + 2) * 32);
        }
        if (++cur == NSTAGE) cur = 0;
    }

    // epilogue: fp32 accum -> C
    const int r0 = bm + wm * 32 + (lid >> 2);
    const int cb = bn + wn * 64 + (lid & 3) * 2;
    #pragma unroll
    for (int t = 0; t < 2; ++t)
        #pragma unroll
        for (int j = 0; j < 8; ++j) {
            float2 v0 = make_float2(acc[t][j][0], acc[t][j][1]);
            float2 v1 = make_float2(acc[t][j][2], acc[t][j][3]);
            *(float2*)(C + (size_t)(r0 + t * 16)     * Cw + cb + j * 8) = v0;
            *(float2*)(C + (size_t)(r0 + t * 16 + 8) * Cw + cb + j * 8) = v1;
        }
}

// ---------------- fused gate + mask + causal conv + Cg gate -----------------
#define CONV_CHUNK 128

__global__ __launch_bounds__(256)
void conv_kernel(const int* __restrict__ mask, const float* __restrict__ conv_w)
{
    const int h  = blockIdx.x * 256 + threadIdx.x;
    const int b  = blockIdx.z;
    const int t0 = blockIdx.y * CONV_CHUNK;

    const float cw0 = conv_w[h * LL + 0];
    const float cw1 = conv_w[h * LL + 1];
    const float cw2 = conv_w[h * LL + 2];
    const float cw3 = conv_w[h * LL + 3];

    float p1 = 0.f, p2 = 0.f, p3 = 0.f;
    #pragma unroll
    for (int d = 3; d >= 1; --d) {
        int t = t0 - d;
        float bx = 0.f;
        if (t >= 0 && mask[b * TT + t] != 0) {
            size_t base = ((size_t)(b * TT + t)) * N3H;
            bx = g_BCx[base + h] * g_BCx[base + 2 * HH + h];
        }
        p3 = p2; p2 = p1; p1 = bx;
    }

    for (int t = t0; t < t0 + CONV_CHUNK; ++t) {
        size_t base = ((size_t)(b * TT + t)) * N3H;
        float Bg = g_BCx[base + h];
        float Cg = g_BCx[base + HH + h];
        float xg = g_BCx[base + 2 * HH + h];
        float bx = (mask[b * TT + t] != 0) ? (Bg * xg) : 0.f;
        float conv = cw0 * p3 + cw1 * p2 + cw2 * p1 + cw3 * bx;
        g_yh[((size_t)(b * TT + t)) * HH + h] = __float2half(Cg * conv);
        p3 = p2; p2 = p1; p1 = bx;
    }
}

// ---------------- launch -----------------------------------------------------
extern "C" void kernel_launch(void* const* d_in, const int* in_sizes, int n_in,
                              void* d_out, int out_size)
{
    const float* x      = (const float*)d_in[0];
    const int*   mask   = (const int*)d_in[1];    // bool widened to int32
    const float* W_in   = (const float*)d_in[2];
    const float* conv_w = (const float*)d_in[3];
    const float* W_out  = (const float*)d_in[4];
    float*       out    = (float*)d_out;

    // prep: convert x to fp16, transpose weights to fp16
    convert_x_kernel<<<(size_t)MROWS * HH / (256 * 4), 256>>>(x);
    transpose_h_kernel<<<dim3(N3H / 32, HH / 32), dim3(32, 8)>>>(W_in, 0, HH, N3H);
    transpose_h_kernel<<<dim3(HH / 32, HH / 32), dim3(32, 8)>>>(W_out, 1, HH, HH);

    // GEMM1: BCx = x @ W_in   (16384x2048 @ 2048x6144)
    gemm_mma_kernel<<<dim3(N3H / 128, MROWS / 128), 256>>>(0, nullptr);

    // gate + conv + gate -> y (fp16)
    conv_kernel<<<dim3(HH / 256, TT / CONV_CHUNK, BB), 256>>>(mask, conv_w);

    // GEMM2: out = y @ W_out  (16384x2048 @ 2048x2048)
    gemm_mma_kernel<<<dim3(HH / 128, MROWS / 128), 256>>>(1, out);
}